// round 5
// baseline (speedup 1.0000x reference)
#include <cuda_runtime.h>
#include <cuda_bf16.h>
#include <cstdint>

// SwitchingLinear: out[b,:] = W[idx[b]] @ x[b]
// B=2048, C=64, IN=OUT=512 fp32.
// ONE fused kernel: per-CTA ballot compaction, split-bf16 HMMA grouped GEMM
// (v=hi+lo; D = Ah*Bh + Ah*Bl + Al*Bh), with 16-row-granular M-skip so
// padding rows (expert counts ~Poisson(32) vs TM=64) cost no tensor work.

#define BB    2048
#define CC    64
#define KIN   512
#define NOUT  512
#define TM    64
#define TN    128
#define KB    32
#define NCH   (KIN / KB)       // 16

__device__ __forceinline__ uint32_t smem_u32(const void* p) {
    uint32_t a;
    asm("{ .reg .u64 t; cvta.to.shared.u64 t, %1; cvt.u32.u64 %0, t; }"
        : "=r"(a) : "l"(p));
    return a;
}

#define SW64(o) ((o) ^ (((o) >> 3) & 0x30))

#define LDSM4(r0, r1, r2, r3, a)                                             \
    asm volatile("ldmatrix.sync.aligned.m8n8.x4.shared.b16 {%0,%1,%2,%3}, [%4];" \
                 : "=r"(r0), "=r"(r1), "=r"(r2), "=r"(r3) : "r"(a))

#define MMA(d, a, b0, b1)                                                    \
    asm volatile("mma.sync.aligned.m16n8k16.row.col.f32.bf16.bf16.f32 "      \
                 "{%0,%1,%2,%3},{%4,%5,%6,%7},{%8,%9},{%0,%1,%2,%3};"        \
                 : "+f"((d)[0]), "+f"((d)[1]), "+f"((d)[2]), "+f"((d)[3])    \
                 : "r"((a)[0]), "r"((a)[1]), "r"((a)[2]), "r"((a)[3]),       \
                   "r"(b0), "r"(b1))

// Split fp32 pair -> bf16x2 hi + bf16x2 lo (lo = v - float(hi)).
__device__ __forceinline__ void cvt2(float f0, float f1, uint32_t& h, uint32_t& l) {
    asm("cvt.rn.bf16x2.f32 %0, %1, %2;" : "=r"(h) : "f"(f1), "f"(f0));
    float h0 = __uint_as_float(h << 16);
    float h1 = __uint_as_float(h & 0xFFFF0000u);
    float l0 = f0 - h0, l1 = f1 - h1;
    asm("cvt.rn.bf16x2.f32 %0, %1, %2;" : "=r"(l) : "f"(l1), "f"(l0));
}

__global__ __launch_bounds__(256, 2)
void k_all(const float* __restrict__ x, const float* __restrict__ w,
           const int* __restrict__ idx, float* __restrict__ out) {
    __shared__ __align__(1024) char sm[49152];

    int t = threadIdx.x, wid = t >> 5, lane = t & 31;
    int e    = blockIdx.x & 63;
    int tile = blockIdx.x >> 6;
    int n0   = blockIdx.y * TN;

    // ---- phase 0: index dtype detect + ballot compaction ----
    int* s_list = (int*)sm;          // [128]
    int* s_wcnt = (int*)(sm + 512);  // [8]
    int* s_flag = (int*)(sm + 552);

    if (t == 0) *s_flag = 0;
    __syncthreads();
    if (t < 128 && idx[2 * t + 1]) atomicOr(s_flag, 1);
    __syncthreads();
    const int is64 = (*s_flag == 0);

    uint32_t bal[8];
    int base = wid * 256;
    {
        int c_w = 0;
#pragma unroll
        for (int j = 0; j < 8; j++) {
            int smp = base + j * 32 + lane;
            int c = is64 ? idx[2 * smp] : idx[smp];
            bal[j] = __ballot_sync(0xffffffffu, c == e);
            c_w += __popc(bal[j]);
        }
        if (lane == 0) s_wcnt[wid] = c_w;
    }
    __syncthreads();
    int woff = 0, cnt = 0;
#pragma unroll
    for (int k = 0; k < 8; k++) {
        int v = s_wcnt[k];
        if (k < wid) woff += v;
        cnt += v;
    }
    if (tile * TM >= cnt) return;     // uniform across CTA

    {
        int run = woff;
#pragma unroll
        for (int j = 0; j < 8; j++) {
            int smp = base + j * 32 + lane;
            if ((bal[j] >> lane) & 1) {
                int pos = run + __popc(bal[j] & ((1u << lane) - 1));
                if (pos < 128) s_list[pos] = smp;
            }
            run += __popc(bal[j]);
        }
    }
    __syncthreads();

    int mcnt = cnt - tile * TM;
    if (mcnt > TM) mcnt = TM;
    const int mceil = (mcnt + 15) & ~15;          // A rows actually consumed
    const int* lst = s_list + tile * TM;

    // Register-resident pulls from s_list before stages overwrite it.
    int lrow = t >> 2;                    // loader row 0..63
    int asrc = (lrow < mcnt) ? lst[lrow] : -1;
    const bool astore = (lrow < mceil);   // store A only for consumed rows

    int mbase = (wid & 1) * 32;
    int nbase = (wid >> 1) * 32;
    // per-warp active m-fragments (16 rows each): 0, 1 or 2
    int mwork = mcnt - mbase;
    int nmf = (mwork <= 0) ? 0 : ((mwork >= 32) ? 2 : ((mwork + 15) >> 4));

    int er0[2], er1[2];
#pragma unroll
    for (int mf = 0; mf < 2; mf++) {
        int m0 = mbase + mf * 16 + (lane >> 2);
        int m1 = m0 + 8;
        er0[mf] = (m0 < mcnt) ? lst[m0] : -1;
        er1[mf] = (m1 < mcnt) ? lst[m1] : -1;
    }
    __syncthreads();                      // scratch dead; stages own sm

    // ---- phase 1: grouped GEMM ----
    const uint32_t sb = smem_u32(sm);
    const float* wc = w + (size_t)e * (NOUT * KIN) + (size_t)n0 * KIN;

    int kf = (t & 3) * 8;
    const float* ap  = x  + (size_t)(asrc < 0 ? 0 : asrc) * KIN + kf;
    const float* bp0 = wc + (size_t)lrow * KIN + kf;
    const float* bp1 = bp0 + (size_t)64 * KIN;

    float4 av[2], bv[4];
    if (asrc >= 0) { av[0] = *(const float4*)ap; av[1] = *(const float4*)(ap + 4); }
    else { av[0] = make_float4(0.f, 0.f, 0.f, 0.f); av[1] = av[0]; }
    bv[0] = *(const float4*)bp0; bv[1] = *(const float4*)(bp0 + 4);
    bv[2] = *(const float4*)bp1; bv[3] = *(const float4*)(bp1 + 4);

    int a_r = (lane & 7) + ((lane >> 3) & 1) * 8;
    int a_c = ((lane >> 4) & 1) * 16;
    int b_r = (lane & 7) + ((lane >> 4) & 1) * 8;
    int b_c = ((lane >> 3) & 1) * 16;

    float acc[2][4][4];
#pragma unroll
    for (int i = 0; i < 2; i++)
#pragma unroll
        for (int j = 0; j < 4; j++)
#pragma unroll
            for (int q = 0; q < 4; q++) acc[i][j][q] = 0.f;

    uint32_t sts  = SW64((uint32_t)(lrow * 64 + (t & 3) * 16));
    uint32_t sts2 = SW64((uint32_t)((lrow + 64) * 64 + (t & 3) * 16));

#pragma unroll 1
    for (int s = 0; s < NCH; s++) {
        char* stg = sm + (s & 1) * 24576;
        {
            uint32_t h0, l0, h1, l1, h2, l2, h3, l3;
            if (astore) {
                cvt2(av[0].x, av[0].y, h0, l0); cvt2(av[0].z, av[0].w, h1, l1);
                cvt2(av[1].x, av[1].y, h2, l2); cvt2(av[1].z, av[1].w, h3, l3);
                *(uint4*)(stg + sts)        = make_uint4(h0, h1, h2, h3);
                *(uint4*)(stg + 4096 + sts) = make_uint4(l0, l1, l2, l3);
            }
            cvt2(bv[0].x, bv[0].y, h0, l0); cvt2(bv[0].z, bv[0].w, h1, l1);
            cvt2(bv[1].x, bv[1].y, h2, l2); cvt2(bv[1].z, bv[1].w, h3, l3);
            *(uint4*)(stg + 8192 + sts)  = make_uint4(h0, h1, h2, h3);
            *(uint4*)(stg + 16384 + sts) = make_uint4(l0, l1, l2, l3);
            cvt2(bv[2].x, bv[2].y, h0, l0); cvt2(bv[2].z, bv[2].w, h1, l1);
            cvt2(bv[3].x, bv[3].y, h2, l2); cvt2(bv[3].z, bv[3].w, h3, l3);
            *(uint4*)(stg + 8192 + sts2)  = make_uint4(h0, h1, h2, h3);
            *(uint4*)(stg + 16384 + sts2) = make_uint4(l0, l1, l2, l3);
        }
        __syncthreads();

        if (s + 1 < NCH) {
            int g = (s + 1) * KB;
            if (asrc >= 0) {
                av[0] = *(const float4*)(ap + g);
                av[1] = *(const float4*)(ap + g + 4);
            }
            bv[0] = *(const float4*)(bp0 + g); bv[1] = *(const float4*)(bp0 + g + 4);
            bv[2] = *(const float4*)(bp1 + g); bv[3] = *(const float4*)(bp1 + g + 4);
        }

        if (nmf > 0) {
            uint32_t bbase = sb + (uint32_t)((s & 1) * 24576);
#pragma unroll
            for (int ks = 0; ks < 2; ks++) {
                uint32_t ah[2][4], al[2][4], bh[2][4], bl[2][4];
#pragma unroll
                for (int mf = 0; mf < 2; mf++) {
                    if (mf < nmf) {
                        uint32_t o = SW64((uint32_t)((mbase + mf * 16 + a_r) * 64 + ks * 32 + a_c));
                        LDSM4(ah[mf][0], ah[mf][1], ah[mf][2], ah[mf][3], bbase + o);
                        LDSM4(al[mf][0], al[mf][1], al[mf][2], al[mf][3], bbase + 4096 + o);
                    }
                }
#pragma unroll
                for (int np = 0; np < 2; np++) {
                    uint32_t o = SW64((uint32_t)((nbase + np * 16 + b_r) * 64 + ks * 32 + b_c));
                    LDSM4(bh[np][0], bh[np][1], bh[np][2], bh[np][3], bbase + 8192 + o);
                    LDSM4(bl[np][0], bl[np][1], bl[np][2], bl[np][3], bbase + 16384 + o);
                }
#pragma unroll
                for (int mf = 0; mf < 2; mf++) {
                    if (mf < nmf) {
#pragma unroll
                        for (int nf = 0; nf < 4; nf++) {
                            int np = nf >> 1, oo = (nf & 1) * 2;
                            MMA(acc[mf][nf], ah[mf], bh[np][oo], bh[np][oo + 1]);
                            MMA(acc[mf][nf], ah[mf], bl[np][oo], bl[np][oo + 1]);
                            MMA(acc[mf][nf], al[mf], bh[np][oo], bh[np][oo + 1]);
                        }
                    }
                }
            }
        }
        __syncthreads();
    }

    // ---- epilogue ----
#pragma unroll
    for (int mf = 0; mf < 2; mf++) {
#pragma unroll
        for (int nf = 0; nf < 4; nf++) {
            int col = n0 + nbase + nf * 8 + (lane & 3) * 2;
            if (er0[mf] >= 0)
                *(float2*)(out + (size_t)er0[mf] * NOUT + col) =
                    make_float2(acc[mf][nf][0], acc[mf][nf][1]);
            if (er1[mf] >= 0)
                *(float2*)(out + (size_t)er1[mf] * NOUT + col) =
                    make_float2(acc[mf][nf][2], acc[mf][nf][3]);
        }
    }
}

extern "C" void kernel_launch(void* const* d_in, const int* in_sizes, int n_in,
                              void* d_out, int out_size) {
    const float* x = 0; const int* idx = 0; const float* w = 0;
    for (int i = 0; i < n_in; i++) {
        if (in_sizes[i] == BB)              idx = (const int*)d_in[i];
        else if (in_sizes[i] == BB * KIN)   x   = (const float*)d_in[i];
        else                                w   = (const float*)d_in[i];
    }
    k_all<<<dim3(2 * CC, NOUT / TN), 256>>>(x, w, idx, (float*)d_out);
}

// round 6
// speedup vs baseline: 1.1515x; 1.1515x over previous
#include <cuda_runtime.h>
#include <cuda_bf16.h>
#include <cstdint>

// SwitchingLinear: out[b,:] = W[idx[b]] @ x[b]
// B=2048, C=64, IN=OUT=512 fp32.
// ONE fused kernel, warp-specialized:
//   warps 4-7: producers  (LDG fp32 -> split-bf16 cvt -> STS into 4-deep ring)
//   warps 0-3: consumers  (LDSM -> HMMA, fp32 accum)
// Split-bf16: v = hi + lo;  D = Ah*Bh + Ah*Bl + Al*Bh.  16-row M-skip.
// Named-barrier full/empty pairs per ring stage; no __syncthreads in mainloop.

#define BB    2048
#define CC    64
#define KIN   512
#define NOUT  512
#define TM    64
#define TN    128
#define KB    32
#define NCH   (KIN / KB)     // 16
#define NSTG  4
#define STGB  24576          // Ah 4K | Al 4K | Bh 8K | Bl 8K
#define RING_OFF 1024
#define SMEM_DYN (RING_OFF + NSTG * STGB)   // 99328

__device__ __forceinline__ uint32_t smem_u32(const void* p) {
    uint32_t a;
    asm("{ .reg .u64 t; cvta.to.shared.u64 t, %1; cvt.u32.u64 %0, t; }"
        : "=r"(a) : "l"(p));
    return a;
}

#define SW64(o) ((o) ^ (((o) >> 3) & 0x30))

#define BAR_SYNC(id)   asm volatile("bar.sync %0, 256;"   :: "r"(id) : "memory")
#define BAR_ARRIVE(id) asm volatile("bar.arrive %0, 256;" :: "r"(id) : "memory")

#define LDSM4(r0, r1, r2, r3, a)                                             \
    asm volatile("ldmatrix.sync.aligned.m8n8.x4.shared.b16 {%0,%1,%2,%3}, [%4];" \
                 : "=r"(r0), "=r"(r1), "=r"(r2), "=r"(r3) : "r"(a))

#define MMA(d, a, b0, b1)                                                    \
    asm volatile("mma.sync.aligned.m16n8k16.row.col.f32.bf16.bf16.f32 "      \
                 "{%0,%1,%2,%3},{%4,%5,%6,%7},{%8,%9},{%0,%1,%2,%3};"        \
                 : "+f"((d)[0]), "+f"((d)[1]), "+f"((d)[2]), "+f"((d)[3])    \
                 : "r"((a)[0]), "r"((a)[1]), "r"((a)[2]), "r"((a)[3]),       \
                   "r"(b0), "r"(b1))

// Split fp32 pair -> bf16x2 hi + bf16x2 lo (lo = v - float(hi)).
__device__ __forceinline__ void cvt2(float f0, float f1, uint32_t& h, uint32_t& l) {
    asm("cvt.rn.bf16x2.f32 %0, %1, %2;" : "=r"(h) : "f"(f1), "f"(f0));
    float h0 = __uint_as_float(h << 16);
    float h1 = __uint_as_float(h & 0xFFFF0000u);
    float l0 = f0 - h0, l1 = f1 - h1;
    asm("cvt.rn.bf16x2.f32 %0, %1, %2;" : "=r"(l) : "f"(l1), "f"(l0));
}

__global__ __launch_bounds__(256, 2)
void k_all(const float* __restrict__ x, const float* __restrict__ w,
           const int* __restrict__ idx, float* __restrict__ out) {
    extern __shared__ __align__(1024) char sm[];

    int t = threadIdx.x, lane = t & 31;
    int e    = blockIdx.x & 63;
    int tile = blockIdx.x >> 6;
    int n0   = blockIdx.y * TN;

    // ---- phase 0: index dtype detect + ballot compaction (scratch < 1KB) ----
    int* s_list = (int*)sm;          // [128]
    int* s_wcnt = (int*)(sm + 512);  // [8]
    int* s_flag = (int*)(sm + 552);

    if (t == 0) *s_flag = 0;
    __syncthreads();
    if (t < 128 && idx[2 * t + 1]) atomicOr(s_flag, 1);
    __syncthreads();
    const int is64 = (*s_flag == 0);

    int wid = t >> 5;
    uint32_t bal[8];
    int base = wid * 256;
    {
        int c_w = 0;
#pragma unroll
        for (int j = 0; j < 8; j++) {
            int smp = base + j * 32 + lane;
            int c = is64 ? idx[2 * smp] : idx[smp];
            bal[j] = __ballot_sync(0xffffffffu, c == e);
            c_w += __popc(bal[j]);
        }
        if (lane == 0) s_wcnt[wid] = c_w;
    }
    __syncthreads();
    int woff = 0, cnt = 0;
#pragma unroll
    for (int k = 0; k < 8; k++) {
        int v = s_wcnt[k];
        if (k < wid) woff += v;
        cnt += v;
    }
    if (tile * TM >= cnt) return;     // uniform across CTA

    {
        int run = woff;
#pragma unroll
        for (int j = 0; j < 8; j++) {
            int smp = base + j * 32 + lane;
            if ((bal[j] >> lane) & 1) {
                int pos = run + __popc(bal[j] & ((1u << lane) - 1));
                if (pos < 128) s_list[pos] = smp;
            }
            run += __popc(bal[j]);
        }
    }
    __syncthreads();

    int mcnt = cnt - tile * TM;
    if (mcnt > TM) mcnt = TM;
    const int* lst = s_list + tile * TM;
    const int nmf = (mcnt + 15) >> 4;          // 1..4 active 16-row frags

    // Per-role register pulls from s_list (before ring overwrites scratch).
    int asr[4];                                 // producer: A source rows
    int er0[4], er1[4];                         // consumer: epilogue rows
    if (t >= 128) {
        int p = t - 128, rb = p >> 3;
#pragma unroll
        for (int j = 0; j < 4; j++) {
            int r = rb + 16 * j;
            asr[j] = (r < mcnt) ? lst[r] : -1;
        }
    } else {
#pragma unroll
        for (int mf = 0; mf < 4; mf++) {
            int m0 = mf * 16 + (lane >> 2);
            int m1 = m0 + 8;
            er0[mf] = (m0 < mcnt) ? lst[m0] : -1;
            er1[mf] = (m1 < mcnt) ? lst[m1] : -1;
        }
    }
    __syncthreads();                            // scratch dead; ring owns sm

    const uint32_t sb = smem_u32(sm);
    const float* wc = w + (size_t)e * (NOUT * KIN) + (size_t)n0 * KIN;

    if (t >= 128) {
        // ================= PRODUCER =================
        int p = t - 128;
        int rb = p >> 3;                        // 0..15
        int col = (p & 7) * 4;                  // float col in 32-chunk
        uint32_t so = SW64((uint32_t)(rb * 64 + (p & 7) * 8));
        uint32_t so16[8];
#pragma unroll
        for (int j = 0; j < 8; j++)
            so16[j] = SW64((uint32_t)((rb + 16 * j) * 64 + (p & 7) * 8));
        (void)so;

#pragma unroll 1
        for (int s = 0; s < NCH; s++) {
            int k0 = s * KB + col;
            float4 av[4];
#pragma unroll
            for (int j = 0; j < 4; j++)
                av[j] = (asr[j] >= 0)
                    ? *(const float4*)(x + (size_t)asr[j] * KIN + k0)
                    : make_float4(0.f, 0.f, 0.f, 0.f);
            float4 bv[8];
#pragma unroll
            for (int j = 0; j < 8; j++)
                bv[j] = *(const float4*)(wc + (size_t)(rb + 16 * j) * KIN + k0);

            if (s >= NSTG) BAR_SYNC(5 + (s & 3));
            char* stg = sm + RING_OFF + (s & 3) * STGB;
#pragma unroll
            for (int j = 0; j < 4; j++) {
                uint32_t h0, l0, h1, l1;
                cvt2(av[j].x, av[j].y, h0, l0);
                cvt2(av[j].z, av[j].w, h1, l1);
                *(uint2*)(stg + so16[j])        = make_uint2(h0, h1);
                *(uint2*)(stg + 4096 + so16[j]) = make_uint2(l0, l1);
            }
#pragma unroll
            for (int j = 0; j < 8; j++) {
                uint32_t h0, l0, h1, l1;
                cvt2(bv[j].x, bv[j].y, h0, l0);
                cvt2(bv[j].z, bv[j].w, h1, l1);
                *(uint2*)(stg + 8192 + so16[j])  = make_uint2(h0, h1);
                *(uint2*)(stg + 16384 + so16[j]) = make_uint2(l0, l1);
            }
            BAR_ARRIVE(1 + (s & 3));
        }
    } else {
        // ================= CONSUMER =================
        int cw = t >> 5;                        // 0..3
        int nbase = cw * 32;
        int a_r = (lane & 7) + ((lane >> 3) & 1) * 8;
        int a_c = ((lane >> 4) & 1) * 16;
        int b_r = (lane & 7) + ((lane >> 4) & 1) * 8;
        int b_c = ((lane >> 3) & 1) * 16;

        float acc[4][4][4];
#pragma unroll
        for (int i = 0; i < 4; i++)
#pragma unroll
            for (int j = 0; j < 4; j++)
#pragma unroll
                for (int q = 0; q < 4; q++) acc[i][j][q] = 0.f;

#pragma unroll 1
        for (int s = 0; s < NCH; s++) {
            BAR_SYNC(1 + (s & 3));
            uint32_t bs = sb + RING_OFF + (uint32_t)((s & 3) * STGB);
#pragma unroll
            for (int ks = 0; ks < 2; ks++) {
                uint32_t bh[2][4], bl[2][4];
#pragma unroll
                for (int np = 0; np < 2; np++) {
                    uint32_t o = SW64((uint32_t)((nbase + np * 16 + b_r) * 64 + ks * 32 + b_c));
                    LDSM4(bh[np][0], bh[np][1], bh[np][2], bh[np][3], bs + 8192 + o);
                    LDSM4(bl[np][0], bl[np][1], bl[np][2], bl[np][3], bs + 16384 + o);
                }
#pragma unroll
                for (int mf = 0; mf < 4; mf++) {
                    if (mf < nmf) {
                        uint32_t ah[4], al[4];
                        uint32_t o = SW64((uint32_t)((mf * 16 + a_r) * 64 + ks * 32 + a_c));
                        LDSM4(ah[0], ah[1], ah[2], ah[3], bs + o);
                        LDSM4(al[0], al[1], al[2], al[3], bs + 4096 + o);
#pragma unroll
                        for (int nf = 0; nf < 4; nf++) {
                            int np = nf >> 1, oo = (nf & 1) * 2;
                            MMA(acc[mf][nf], ah, bh[np][oo], bh[np][oo + 1]);
                            MMA(acc[mf][nf], ah, bl[np][oo], bl[np][oo + 1]);
                            MMA(acc[mf][nf], al, bh[np][oo], bh[np][oo + 1]);
                        }
                    }
                }
            }
            BAR_ARRIVE(5 + (s & 3));
        }

        // ---- epilogue ----
#pragma unroll
        for (int mf = 0; mf < 4; mf++) {
#pragma unroll
            for (int nf = 0; nf < 4; nf++) {
                int col = n0 + nbase + nf * 8 + (lane & 3) * 2;
                if (er0[mf] >= 0)
                    *(float2*)(out + (size_t)er0[mf] * NOUT + col) =
                        make_float2(acc[mf][nf][0], acc[mf][nf][1]);
                if (er1[mf] >= 0)
                    *(float2*)(out + (size_t)er1[mf] * NOUT + col) =
                        make_float2(acc[mf][nf][2], acc[mf][nf][3]);
            }
        }
    }
}

extern "C" void kernel_launch(void* const* d_in, const int* in_sizes, int n_in,
                              void* d_out, int out_size) {
    const float* x = 0; const int* idx = 0; const float* w = 0;
    for (int i = 0; i < n_in; i++) {
        if (in_sizes[i] == BB)              idx = (const int*)d_in[i];
        else if (in_sizes[i] == BB * KIN)   x   = (const float*)d_in[i];
        else                                w   = (const float*)d_in[i];
    }
    cudaFuncSetAttribute(k_all, cudaFuncAttributeMaxDynamicSharedMemorySize, SMEM_DYN);
    k_all<<<dim3(2 * CC, NOUT / TN), 256, SMEM_DYN>>>(x, w, idx, (float*)d_out);
}

// round 7
// speedup vs baseline: 1.1530x; 1.0013x over previous
#include <cuda_runtime.h>
#include <cuda_bf16.h>
#include <cstdint>

// SwitchingLinear: out[b,:] = W[idx[b]] @ x[b]
// B=2048, C=64, IN=OUT=512 fp32.
// ONE fused kernel, warp-specialized producer/consumer with a 4-deep ring:
//   warps 4-7: producers (LDG fp32 -> split-bf16 cvt -> STS), software-
//              pipelined in half-stages so next-stage DRAM latency hides
//              under current-stage cvt+STS.
//   warps 0-3: consumers (LDSM -> HMMA, fp32 accum), 16-row M-skip.
// Split-bf16: v = hi + lo;  D = Ah*Bh + Ah*Bl + Al*Bh.
// Grid = (expert, n-block): 256 CTAs, zero dead blocks; rare count>64
// handled by an in-CTA tile loop (global stage counter keys ring+barriers).

#define BB    2048
#define CC    64
#define KIN   512
#define NOUT  512
#define TM    64
#define TN    128
#define KB    32
#define NCH   (KIN / KB)     // 16
#define NSTG  4
#define STGB  24576          // Ah 4K | Al 4K | Bh 8K | Bl 8K
#define RING_OFF 1024
#define SMEM_DYN (RING_OFF + NSTG * STGB)   // 99328

__device__ __forceinline__ uint32_t smem_u32(const void* p) {
    uint32_t a;
    asm("{ .reg .u64 t; cvta.to.shared.u64 t, %1; cvt.u32.u64 %0, t; }"
        : "=r"(a) : "l"(p));
    return a;
}

#define SW64(o) ((o) ^ (((o) >> 3) & 0x30))

#define BAR_SYNC(id)   asm volatile("bar.sync %0, 256;"   :: "r"(id) : "memory")
#define BAR_ARRIVE(id) asm volatile("bar.arrive %0, 256;" :: "r"(id) : "memory")

#define LDSM4(r0, r1, r2, r3, a)                                             \
    asm volatile("ldmatrix.sync.aligned.m8n8.x4.shared.b16 {%0,%1,%2,%3}, [%4];" \
                 : "=r"(r0), "=r"(r1), "=r"(r2), "=r"(r3) : "r"(a))

#define MMA(d, a, b0, b1)                                                    \
    asm volatile("mma.sync.aligned.m16n8k16.row.col.f32.bf16.bf16.f32 "      \
                 "{%0,%1,%2,%3},{%4,%5,%6,%7},{%8,%9},{%0,%1,%2,%3};"        \
                 : "+f"((d)[0]), "+f"((d)[1]), "+f"((d)[2]), "+f"((d)[3])    \
                 : "r"((a)[0]), "r"((a)[1]), "r"((a)[2]), "r"((a)[3]),       \
                   "r"(b0), "r"(b1))

// Split fp32 pair -> bf16x2 hi + bf16x2 lo (lo = v - float(hi)).
__device__ __forceinline__ void cvt2(float f0, float f1, uint32_t& h, uint32_t& l) {
    asm("cvt.rn.bf16x2.f32 %0, %1, %2;" : "=r"(h) : "f"(f1), "f"(f0));
    float h0 = __uint_as_float(h << 16);
    float h1 = __uint_as_float(h & 0xFFFF0000u);
    float l0 = f0 - h0, l1 = f1 - h1;
    asm("cvt.rn.bf16x2.f32 %0, %1, %2;" : "=r"(l) : "f"(l1), "f"(l0));
}

__device__ __forceinline__ void cvt_sts(const float4& v, char* hp, char* lp) {
    uint32_t h0, l0, h1, l1;
    cvt2(v.x, v.y, h0, l0);
    cvt2(v.z, v.w, h1, l1);
    *(uint2*)hp = make_uint2(h0, h1);
    *(uint2*)lp = make_uint2(l0, l1);
}

__global__ __launch_bounds__(256, 2)
void k_all(const float* __restrict__ x, const float* __restrict__ w,
           const int* __restrict__ idx, float* __restrict__ out) {
    extern __shared__ __align__(1024) char sm[];

    int t = threadIdx.x, lane = t & 31;
    int e  = blockIdx.x;
    int n0 = blockIdx.y * TN;

    // ---- phase 0: index dtype detect + ballot compaction (scratch < 1KB) ----
    int* s_list = (int*)sm;          // [128], persists below the ring
    int* s_wcnt = (int*)(sm + 512);
    int* s_flag = (int*)(sm + 552);

    if (t == 0) *s_flag = 0;
    __syncthreads();
    if (t < 128 && idx[2 * t + 1]) atomicOr(s_flag, 1);
    __syncthreads();
    const int is64 = (*s_flag == 0);

    int wid = t >> 5;
    uint32_t bal[8];
    int base = wid * 256;
    {
        int c_w = 0;
#pragma unroll
        for (int j = 0; j < 8; j++) {
            int smp = base + j * 32 + lane;
            int c = is64 ? idx[2 * smp] : idx[smp];
            bal[j] = __ballot_sync(0xffffffffu, c == e);
            c_w += __popc(bal[j]);
        }
        if (lane == 0) s_wcnt[wid] = c_w;
    }
    __syncthreads();
    int woff = 0, cnt = 0;
#pragma unroll
    for (int k = 0; k < 8; k++) {
        int v = s_wcnt[k];
        if (k < wid) woff += v;
        cnt += v;
    }
    {
        int run = woff;
#pragma unroll
        for (int j = 0; j < 8; j++) {
            int smp = base + j * 32 + lane;
            if ((bal[j] >> lane) & 1) {
                int pos = run + __popc(bal[j] & ((1u << lane) - 1));
                if (pos < 128) s_list[pos] = smp;
            }
            run += __popc(bal[j]);
        }
    }
    __syncthreads();          // s_list final; never written again

    if (cnt == 0) return;     // uniform
    int ntiles = (cnt + TM - 1) / TM;
    if (ntiles > 2) ntiles = 2;

    const float* wc = w + (size_t)e * (NOUT * KIN) + (size_t)n0 * KIN;
    const uint32_t sb = smem_u32(sm);

    if (t >= 128) {
        // ================= PRODUCER =================
        int p   = t - 128;
        int rb  = p >> 3;                       // 0..15
        int col = (p & 7) * 4;                  // float col in 32-chunk
        uint32_t so16[8];
#pragma unroll
        for (int j = 0; j < 8; j++)
            so16[j] = SW64((uint32_t)((rb + 16 * j) * 64 + (p & 7) * 8));
        const float* bpp[8];
#pragma unroll
        for (int j = 0; j < 8; j++)
            bpp[j] = wc + (size_t)(rb + 16 * j) * KIN + col;

#pragma unroll 1
        for (int tile = 0; tile < ntiles; tile++) {
            int tb = tile * TM;
            int mcnt = cnt - tb;
            if (mcnt > TM) mcnt = TM;
            int asr[4];
#pragma unroll
            for (int j = 0; j < 4; j++) {
                int r = rb + 16 * j;
                asr[j] = (r < mcnt) ? s_list[tb + r] : -1;
            }
            // Prologue: load stage 0 halves.
            float4 A[4], B0[4], B1[4];
#pragma unroll
            for (int j = 0; j < 4; j++)
                A[j] = (asr[j] >= 0)
                    ? *(const float4*)(x + (size_t)asr[j] * KIN + col)
                    : make_float4(0.f, 0.f, 0.f, 0.f);
#pragma unroll
            for (int j = 0; j < 4; j++) B0[j] = *(const float4*)bpp[j];
#pragma unroll
            for (int j = 0; j < 4; j++) B1[j] = *(const float4*)bpp[j + 4];

#pragma unroll 1
            for (int s = 0; s < NCH; s++) {
                int sg = tile * NCH + s;
                if (sg >= NSTG) BAR_SYNC(5 + (sg & 3));
                char* stg = sm + RING_OFF + (sg & 3) * STGB;

                // Half 0: A + B rows 0..63
#pragma unroll
                for (int j = 0; j < 4; j++)
                    cvt_sts(A[j], stg + so16[j], stg + 4096 + so16[j]);
#pragma unroll
                for (int j = 0; j < 4; j++)
                    cvt_sts(B0[j], stg + 8192 + so16[j], stg + 16384 + so16[j]);
                // Issue next-stage H0 loads now (hide latency under H1 cvt).
                if (s + 1 < NCH) {
                    int g = (s + 1) * KB;
#pragma unroll
                    for (int j = 0; j < 4; j++)
                        A[j] = (asr[j] >= 0)
                            ? *(const float4*)(x + (size_t)asr[j] * KIN + g + col)
                            : make_float4(0.f, 0.f, 0.f, 0.f);
#pragma unroll
                    for (int j = 0; j < 4; j++)
                        B0[j] = *(const float4*)(bpp[j] + g);
                }
                // Half 1: B rows 64..127
#pragma unroll
                for (int j = 0; j < 4; j++)
                    cvt_sts(B1[j], stg + 8192 + so16[j + 4], stg + 16384 + so16[j + 4]);
                if (s + 1 < NCH) {
                    int g = (s + 1) * KB;
#pragma unroll
                    for (int j = 0; j < 4; j++)
                        B1[j] = *(const float4*)(bpp[j + 4] + g);
                }
                BAR_ARRIVE(1 + (sg & 3));
            }
        }
    } else {
        // ================= CONSUMER =================
        int cw = t >> 5;                        // 0..3
        int nbase = cw * 32;
        int a_r = (lane & 7) + ((lane >> 3) & 1) * 8;
        int a_c = ((lane >> 4) & 1) * 16;
        int b_r = (lane & 7) + ((lane >> 4) & 1) * 8;
        int b_c = ((lane >> 3) & 1) * 16;

#pragma unroll 1
        for (int tile = 0; tile < ntiles; tile++) {
            int tb = tile * TM;
            int mcnt = cnt - tb;
            if (mcnt > TM) mcnt = TM;
            const int nmf = (mcnt + 15) >> 4;   // 1..4 active 16-row frags

            float acc[4][4][4];
#pragma unroll
            for (int i = 0; i < 4; i++)
#pragma unroll
                for (int j = 0; j < 4; j++)
#pragma unroll
                    for (int q = 0; q < 4; q++) acc[i][j][q] = 0.f;

#pragma unroll 1
            for (int s = 0; s < NCH; s++) {
                int sg = tile * NCH + s;
                BAR_SYNC(1 + (sg & 3));
                uint32_t bs = sb + RING_OFF + (uint32_t)((sg & 3) * STGB);
#pragma unroll
                for (int ks = 0; ks < 2; ks++) {
                    uint32_t bh[2][4], bl[2][4];
#pragma unroll
                    for (int np = 0; np < 2; np++) {
                        uint32_t o = SW64((uint32_t)((nbase + np * 16 + b_r) * 64 + ks * 32 + b_c));
                        LDSM4(bh[np][0], bh[np][1], bh[np][2], bh[np][3], bs + 8192 + o);
                        LDSM4(bl[np][0], bl[np][1], bl[np][2], bl[np][3], bs + 16384 + o);
                    }
#pragma unroll
                    for (int mf = 0; mf < 4; mf++) {
                        if (mf < nmf) {
                            uint32_t ah[4], al[4];
                            uint32_t o = SW64((uint32_t)((mf * 16 + a_r) * 64 + ks * 32 + a_c));
                            LDSM4(ah[0], ah[1], ah[2], ah[3], bs + o);
                            LDSM4(al[0], al[1], al[2], al[3], bs + 4096 + o);
#pragma unroll
                            for (int nf = 0; nf < 4; nf++) {
                                int np = nf >> 1, oo = (nf & 1) * 2;
                                MMA(acc[mf][nf], ah, bh[np][oo], bh[np][oo + 1]);
                                MMA(acc[mf][nf], ah, bl[np][oo], bl[np][oo + 1]);
                                MMA(acc[mf][nf], al, bh[np][oo], bh[np][oo + 1]);
                            }
                        }
                    }
                }
                BAR_ARRIVE(5 + (sg & 3));
            }

            // ---- epilogue (s_list persists below ring) ----
#pragma unroll
            for (int mf = 0; mf < 4; mf++) {
                int m0 = mf * 16 + (lane >> 2);
                int m1 = m0 + 8;
                int r0 = (m0 < mcnt) ? s_list[tb + m0] : -1;
                int r1 = (m1 < mcnt) ? s_list[tb + m1] : -1;
#pragma unroll
                for (int nf = 0; nf < 4; nf++) {
                    int col = n0 + nbase + nf * 8 + (lane & 3) * 2;
                    if (r0 >= 0)
                        *(float2*)(out + (size_t)r0 * NOUT + col) =
                            make_float2(acc[mf][nf][0], acc[mf][nf][1]);
                    if (r1 >= 0)
                        *(float2*)(out + (size_t)r1 * NOUT + col) =
                            make_float2(acc[mf][nf][2], acc[mf][nf][3]);
                }
            }
        }
    }
}

extern "C" void kernel_launch(void* const* d_in, const int* in_sizes, int n_in,
                              void* d_out, int out_size) {
    const float* x = 0; const int* idx = 0; const float* w = 0;
    for (int i = 0; i < n_in; i++) {
        if (in_sizes[i] == BB)              idx = (const int*)d_in[i];
        else if (in_sizes[i] == BB * KIN)   x   = (const float*)d_in[i];
        else                                w   = (const float*)d_in[i];
    }
    cudaFuncSetAttribute(k_all, cudaFuncAttributeMaxDynamicSharedMemorySize, SMEM_DYN);
    k_all<<<dim3(CC, NOUT / TN), 256, SMEM_DYN>>>(x, w, idx, (float*)d_out);
}